// round 15
// baseline (speedup 1.0000x reference)
#include <cuda_runtime.h>
#include <stdint.h>

// Problem constants (from reference setup_inputs)
#define BSZ      32
#define XMAX     1024
#define VOCAB    1000
#define YMAX     128
#define LSTATES  257                   // 2*YMAX + 1
#define LOGZERO  (-1e10f)
#define GROW     132                   // compact gathered row floats: 128 tok + blank + pad
#define NTH      256                   // 8 warps
#define NW       8
#define REF      16                    // refresh period (steps)

#define MASK_ELEMS ((size_t)BSZ * (YMAX + 1) * XMAX)   // 32*129*1024

// cross-kernel scratch (static device globals: allocation-guard legal)
__device__ __align__(16) float g_gather[(size_t)BSZ * XMAX * GROW];  // ~17 MB
__device__ __align__(16) float g_blank[BSZ * XMAX];                  // 128 KB
__device__ __align__(16) short g_csum[BSZ * XMAX];
__device__ int   g_ssv[BSZ];

// dynamic smem: bp codes [XMAX][128] bytes (4 states per byte, ownership layout)
extern __shared__ uint8_t bp_sm[];

// ---------------- Stage 1: compact time-invariant gather ----------------
__global__ __launch_bounds__(256)
void fanat_gather(const float* __restrict__ ctc,
                  const int*   __restrict__ ys,
                  const int*   __restrict__ blank_p)
{
    const int idx = blockIdx.x * 256 + threadIdx.x;
    const int total = BSZ * XMAX * GROW;
    if (idx >= total) return;
    const int j  = idx % GROW;
    if (j > 128) return;
    const int bt = idx / GROW;              // b*XMAX + t
    const int b  = bt >> 10;                // XMAX = 1024

    const int blank = blank_p ? blank_p[0] : 0;
    const int tok = (j < 128) ? ys[b * YMAX + j] : blank;
    const float v = ctc[(size_t)bt * VOCAB + tok];
    g_gather[(size_t)bt * GROW + j] = v;
    if (j == 128) g_blank[bt] = v;
}

// ---------------- Stage 2: 8-warp-per-batch Viterbi (2 states/lane) ----------------
__global__ __launch_bounds__(NTH, 1)
void fanat_forward(const int*   __restrict__ src_size,
                   const int*   __restrict__ ys,
                   const int*   __restrict__ ylens,
                   const int*   __restrict__ blank_p,
                   float*       __restrict__ out)
{
    __shared__ float  alphaAt[LSTATES];
    __shared__ short  states_sh[XMAX];
    __shared__ float2 pub[NW * 16];
    __shared__ int    wsum[NW];
    __shared__ int    start_sh;

    const int b    = blockIdx.x;
    const int tid  = threadIdx.x;
    const int w    = tid >> 5;
    const int lane = tid & 31;

    const int blank = blank_p ? blank_p[0] : 0;
    const int ss = src_size[b];
    const int yl = ylens[b];
    const int pl = 2 * yl + 1;

    const int bw = 32 * w;
    const int s0 = bw + 2 * lane;          // even state; lane also does s0+1

    const bool oF0 = s0 >= pl, oF1 = (s0 + 1) >= pl;

    // odd-state token column (clamped for padding lanes) + same_tr flag
    int i1 = 16 * w + lane;
    if (i1 > 127) i1 = 127;
    bool same1;
    {
        const int p1 = (i1 > 0) ? (i1 - 1) : 0;
        same1 = (s0 + 1 == 1) ? true : (ys[b * YMAX + i1] == ys[b * YMAX + p1]);
    }

    const float* tok_base = g_gather + (size_t)b * XMAX * GROW + i1;
    const float* blk_base = g_blank + b * XMAX;

    float a0 = LOGZERO, a1 = LOGZERO;
    if (w == 0 && lane == 0) a0 = 0.0f;    // alpha0[0] = 0

    const int bp_col = 16 * w + (lane >> 1);
    const bool store_lane = ((lane & 1) == 0);

    auto step = [&](int t, float tok, float lb) {
        float h1 = __shfl_up_sync(0xffffffffu, a1, 1);   // alpha[s0-1]
        if (lane == 0) h1 = LOGZERO;
        // even state s0: m0=a0, m1=h1, m2=LOGZERO
        float b0 = fmaxf(a0, h1);
        int   g0 = (h1 > a0) ? 1 : 0;                    // first-max tie-break
        float n0 = (oF0 ? LOGZERO : b0) + lb;
        // odd state s0+1: m0=a1, m1=a0, m2=same?LZ:h1
        float b1 = fmaxf(a1, a0);
        int   g1 = (a0 > a1) ? 1 : 0;
        const float m2 = same1 ? LOGZERO : h1;
        if (m2 > b1) { b1 = m2; g1 = 2; }
        float n1 = (oF1 ? LOGZERO : b1) + tok;

        int code = g0 | (g1 << 2);                       // 4 bits
        const int oc = __shfl_down_sync(0xffffffffu, code, 1);
        if (store_lane) bp_sm[t * 128 + bp_col] = (uint8_t)(code | (oc << 4));
        a0 = n0; a1 = n1;
    };

    auto refresh = [&]() {
        if (lane >= 16) pub[w * 16 + (lane - 16)] = make_float2(a0, a1);
        __syncthreads();
        if (w > 0 && lane < 16) {
            const float2 v = pub[(w - 1) * 16 + lane];
            a0 = v.x; a1 = v.y;
        }
        __syncthreads();
    };

    // -------- register prefetch: 8-row token buffers + blank float4 pairs ----
    float tA[8], tB[8];
    float4 bA0, bA1, bB0, bB1;
    auto ldrow = [&](int r) -> float {
        int rp = (r < XMAX) ? r : (XMAX - 1);
        return __ldg(tok_base + (size_t)rp * GROW);
    };
    auto ldblk4 = [&](int t) -> float4 {
        int tp = (t <= XMAX - 4) ? t : (XMAX - 4);
        return *(const float4*)(blk_base + tp);
    };
#pragma unroll
    for (int i = 0; i < 8; i++) tA[i] = ldrow(i);
    bA0 = ldblk4(0); bA1 = ldblk4(4);

    int t0 = 0;
    while (t0 + 8 <= ss) {
        // prefetch next halfblock
#pragma unroll
        for (int i = 0; i < 8; i++) tB[i] = ldrow(t0 + 8 + i);
        bB0 = ldblk4(t0 + 8); bB1 = ldblk4(t0 + 12);
        // 8 unconditional steps from A
        step(t0 + 0, tA[0], bA0.x);
        step(t0 + 1, tA[1], bA0.y);
        step(t0 + 2, tA[2], bA0.z);
        step(t0 + 3, tA[3], bA0.w);
        step(t0 + 4, tA[4], bA1.x);
        step(t0 + 5, tA[5], bA1.y);
        step(t0 + 6, tA[6], bA1.z);
        step(t0 + 7, tA[7], bA1.w);
#pragma unroll
        for (int i = 0; i < 8; i++) tA[i] = tB[i];
        bA0 = bB0; bA1 = bB1;
        t0 += 8;
        if ((t0 & (REF - 1)) == 0 && t0 < ss) refresh();
    }
    {   // tail < 8 steps; A holds rows t0..t0+7
        const float bl[8] = {bA0.x, bA0.y, bA0.z, bA0.w, bA1.x, bA1.y, bA1.z, bA1.w};
#pragma unroll
        for (int i = 0; i < 8; i++)
            if (t0 + i < ss) step(t0 + i, tA[i], bl[i]);
    }

    // ---- publish owned alpha at t = ss ----
    {
        const int olo = (w == 0) ? 0 : bw + 32;
        if (s0 >= olo && s0 < LSTATES)     alphaAt[s0]     = a0;
        if (s0 + 1 >= olo && s0 + 1 < LSTATES) alphaAt[s0 + 1] = a1;
    }
    for (int t = ss + tid; t < XMAX; t += NTH) states_sh[t] = 0;
    __syncthreads();

    if (tid == 0) {
        const float v1 = alphaAt[pl - 1];
        const float v2 = alphaAt[pl - 2];
        start_sh = (v1 > v2) ? (pl - 1) : (pl - 2);
        out[b] = fmaxf(v1, v2);                              // score
        out[32 + MASK_ELEMS + b] = (float)(yl + 1);          // ylens + 1
    }
    __syncthreads();

    // ---- backtrace (tid 0, ownership-based decode) ----
    if (tid == 0) {
        int carry = start_sh;
        states_sh[ss - 1] = (short)carry;
        for (int t = ss - 2; t >= 0; --t) {
            const int s   = carry;
            const int w0  = (s < 64) ? 0 : ((s >> 5) - 1);
            const int loc = s - 32 * w0;
            const uint8_t byte = bp_sm[(t + 1) * 128 + 16 * w0 + (loc >> 2)];
            carry = s - (int)((byte >> ((loc & 3) * 2)) & 3u);
            states_sh[t] = (short)carry;
        }
    }
    __syncthreads();

    // ---- collapse repeats + exclusive non-blank count (4 t's per thread) ----
    const int t_base = tid * 4;
    int prevTok = 0;
    if (t_base > 0) {
        const int sp = states_sh[t_base - 1];
        prevTok = (sp & 1) ? ys[b * YMAX + ((sp - 1) >> 1)] : blank;
    }
    int lsum = 0;
    {
        int pt = prevTok;
#pragma unroll
        for (int i = 0; i < 4; i++) {
            const int st = states_sh[t_base + i];
            const int tk = (st & 1) ? ys[b * YMAX + ((st - 1) >> 1)] : blank;
            const int col = (tk == pt) ? 0 : tk;
            lsum += (col != blank) ? 1 : 0;
            pt = tk;
        }
    }
    int offs = lsum;
#pragma unroll
    for (int d = 1; d < 32; d <<= 1) {
        const int v = __shfl_up_sync(0xffffffffu, offs, d);
        if (lane >= d) offs += v;
    }
    if (lane == 31) wsum[w] = offs;       // warp total (inclusive)
    offs -= lsum;                          // exclusive within warp
    __syncthreads();
    for (int ww = 0; ww < w; ++ww) offs += wsum[ww];
    {
        int pt = prevTok, run = offs;
#pragma unroll
        for (int i = 0; i < 4; i++) {
            const int t = t_base + i;
            g_csum[b * XMAX + t] = (short)run;
            const int st = states_sh[t];
            const int tk = (st & 1) ? ys[b * YMAX + ((st - 1) >> 1)] : blank;
            const int col = (tk == pt) ? 0 : tk;
            run += (col != blank) ? 1 : 0;
            pt = tk;
        }
    }
    if (tid == 0) g_ssv[b] = ss;
}

// ---------------- Stage 3: trigger_mask streaming store ----------------
__global__ __launch_bounds__(256)
void fanat_mask(float* __restrict__ out)
{
    const int bb   = blockIdx.y;
    const int idx4 = blockIdx.x * 256 + threadIdx.x;        // [0, 33024)
    const int rem  = idx4 * 4;                              // [0, 132096)
    const int j    = rem >> 10;                             // XMAX = 1024
    const int t0   = rem & (XMAX - 1);

    const int ss = g_ssv[bb];
    const short4 cs = *(const short4*)(g_csum + bb * XMAX + t0);
    const int cv[4] = {cs.x, cs.y, cs.z, cs.w};

    float4 v;
    float* vv = &v.x;
#pragma unroll
    for (int u = 0; u < 4; u++) {
        const int t = t0 + u;
        const bool in = (t < ss);
        const int c = cv[u];
        bool r;
        if (j < YMAX) r = in && (c == j);
        else          r = in && (c == YMAX || t == ss - 1);
        vv[u] = r ? 1.0f : 0.0f;
    }
    const size_t e = (size_t)bb * ((YMAX + 1) * XMAX) + rem;
    *(float4*)(out + 32 + e) = v;
}

extern "C" void kernel_launch(void* const* d_in, const int* in_sizes, int n_in,
                              void* d_out, int out_size)
{
    // metadata order: ctc_out(f32), src_mask(bool, unused), src_size(i32),
    //                 ys(i32), ylens(i32), blank(i32 scalar)
    const float* ctc      = (const float*)d_in[0];
    const int*   src_size = (const int*)d_in[2];
    const int*   ys       = (const int*)d_in[3];
    const int*   ylens    = (const int*)d_in[4];
    const int*   blank_p  = (n_in > 5) ? (const int*)d_in[5] : nullptr;

    {   // Stage 1: gather (compact layout + blank column)
        const int total = BSZ * XMAX * GROW;
        fanat_gather<<<(total + 255) / 256, 256>>>(ctc, ys, blank_p);
    }

    {   // Stage 2: forward Viterbi + backtrace + csum
        const int smem = XMAX * 128;                        // 128 KB bp codes
        cudaFuncSetAttribute(fanat_forward,
                             cudaFuncAttributeMaxDynamicSharedMemorySize, smem);
        fanat_forward<<<BSZ, NTH, smem>>>(src_size, ys, ylens, blank_p, (float*)d_out);
    }

    {   // Stage 3: trigger_mask
        dim3 grid((YMAX + 1) * XMAX / 4 / 256, BSZ);        // (129, 32)
        fanat_mask<<<grid, 256>>>((float*)d_out);
    }
}